// round 2
// baseline (speedup 1.0000x reference)
#include <cuda_runtime.h>

#define BSZ 128
#define TN  512
#define UN  1024
#define ON  1024
#define TP1 513

// Scratch (static device globals — no allocation in kernel_launch)
__device__ float g_E [(size_t)TN * BSZ * UN];        // [t*128+b, 1024]
__device__ float g_ZK[(size_t)TN * BSZ * 4 * UN];    // [t*128+b, 4096]  (= E@W_k + b_r)
__device__ float g_H [(size_t)(TN + 1) * BSZ * UN];  // slot 0 = h0, slot t+1 = h after step t
__device__ float g_C [(size_t)BSZ * UN];

__global__ void init_state_kernel(const float* __restrict__ h0, const float* __restrict__ c0) {
    int i = blockIdx.x * blockDim.x + threadIdx.x;
    if (i < BSZ * UN) { g_H[i] = h0[i]; g_C[i] = c0[i]; }
}

// Generic fused SGEMM: C = A[M,1024] @ Bw[1024,N] + bias, tile 128x128x16, 256 thr, 8x8/thread.
// mode 0: A = target_inputs (row r -> b=r&127,t=r>>7, stride 513*1024), relu, C row-major N
// mode 1: A = g_E contiguous, C row-major N (=4096)
// mode 2: A = g_H+1slot contiguous, C = d_out scattered (row r=t*128+b -> [b,t,:])
__global__ __launch_bounds__(256) void sgemm_fused(
    const float* __restrict__ A, const float* __restrict__ Bw,
    const float* __restrict__ bias, float* __restrict__ C,
    int N, int mode)
{
    __shared__ float As[16][128];
    __shared__ float Bs[16][128];

    const int tid = threadIdx.x;
    const int bm = blockIdx.y, bn = blockIdx.x;

    // A-tile load mapping: thread loads 2 float4 from one row
    const int arow = bm * 128 + (tid >> 1);
    const int akoff = (tid & 1) * 8;
    const float* Aptr;
    if (mode == 0) {
        int b = arow & 127, t = arow >> 7;
        Aptr = A + ((size_t)b * TP1 + (size_t)t) * 1024;
    } else {
        Aptr = A + (size_t)arow * 1024;
    }

    // B-tile load mapping: thread loads 2 float4 from row kk=tid>>4
    const int bkk = tid >> 4;
    const int bn4 = (tid & 15) * 8;

    // compute mapping
    const int tm = (tid >> 4) * 8;
    const int tn = (tid & 15) * 8;

    float acc[8][8];
#pragma unroll
    for (int i = 0; i < 8; i++)
#pragma unroll
        for (int j = 0; j < 8; j++) acc[i][j] = 0.f;

    for (int k0 = 0; k0 < 1024; k0 += 16) {
        float4 a0 = *(const float4*)(Aptr + k0 + akoff);
        float4 a1 = *(const float4*)(Aptr + k0 + akoff + 4);
        const float* bsrc = Bw + (size_t)(k0 + bkk) * N + (size_t)bn * 128 + bn4;
        float4 b0 = *(const float4*)(bsrc);
        float4 b1 = *(const float4*)(bsrc + 4);

        __syncthreads();
        {
            int am = tid >> 1;
            As[akoff + 0][am] = a0.x; As[akoff + 1][am] = a0.y;
            As[akoff + 2][am] = a0.z; As[akoff + 3][am] = a0.w;
            As[akoff + 4][am] = a1.x; As[akoff + 5][am] = a1.y;
            As[akoff + 6][am] = a1.z; As[akoff + 7][am] = a1.w;
            *(float4*)&Bs[bkk][bn4]     = b0;
            *(float4*)&Bs[bkk][bn4 + 4] = b1;
        }
        __syncthreads();

#pragma unroll
        for (int kk = 0; kk < 16; kk++) {
            float a[8], b[8];
            *(float4*)(a)     = *(const float4*)&As[kk][tm];
            *(float4*)(a + 4) = *(const float4*)&As[kk][tm + 4];
            *(float4*)(b)     = *(const float4*)&Bs[kk][tn];
            *(float4*)(b + 4) = *(const float4*)&Bs[kk][tn + 4];
#pragma unroll
            for (int i = 0; i < 8; i++)
#pragma unroll
                for (int j = 0; j < 8; j++)
                    acc[i][j] += a[i] * b[j];
        }
    }

    const int grow0 = bm * 128 + tm;
    const int gcol0 = bn * 128 + tn;
    float bv[8];
#pragma unroll
    for (int j = 0; j < 8; j++) bv[j] = bias[gcol0 + j];

#pragma unroll
    for (int i = 0; i < 8; i++) {
        int r = grow0 + i;
        float o[8];
#pragma unroll
        for (int j = 0; j < 8; j++) {
            float v = acc[i][j] + bv[j];
            if (mode == 0) v = v > 0.f ? v : 0.f;
            o[j] = v;
        }
        float* dst;
        if (mode == 2) {
            int b = r & 127, t = r >> 7;
            dst = C + ((size_t)b * TN + (size_t)t) * 1024 + gcol0;
        } else {
            dst = C + (size_t)r * N + gcol0;
        }
        *(float4*)(dst)     = *(const float4*)(o);
        *(float4*)(dst + 4) = *(const float4*)(o + 4);
    }
}

__device__ __forceinline__ float sigmoidf_(float x) { return 1.f / (1.f + expf(-x)); }

// One recurrent step: z = ZK[t] + h_{t} @ W_r (4 gate segments computed together),
// gate math, update c in place, write h_{t+1}.
// Grid: 128 CTAs (each owns 8 gate-columns x all 4 gates x 128 rows), 256 threads.
__global__ __launch_bounds__(256) void lstm_step_kernel(const float* __restrict__ Wr, int t)
{
    __shared__ float hs[32][128];     // [k][row]
    __shared__ float ws[4][32][8];    // [gate][k][col]

    const int tid = threadIdx.x;
    const int j0 = blockIdx.x * 8;

    const float* __restrict__ Hprev = g_H + (size_t)t * (BSZ * UN);

    // h-tile load: thread -> row tid>>1, 16 k-floats at (tid&1)*16
    const int hrow = tid >> 1;
    const int hkoff = (tid & 1) * 16;
    // w-tile load: (g, kk, q) from tid
    const int wg_ = tid >> 6;
    const int wkk = (tid >> 1) & 31;
    const int wq = tid & 1;

    // compute mapping: col j, row quad rq
    const int j = tid & 7;
    const int rq = tid >> 3;

    float ai[4] = {0.f, 0.f, 0.f, 0.f};
    float af[4] = {0.f, 0.f, 0.f, 0.f};
    float ag[4] = {0.f, 0.f, 0.f, 0.f};
    float ao[4] = {0.f, 0.f, 0.f, 0.f};

    for (int k0 = 0; k0 < 1024; k0 += 32) {
        float4 hv[4];
#pragma unroll
        for (int q = 0; q < 4; q++)
            hv[q] = *(const float4*)(Hprev + (size_t)hrow * 1024 + k0 + hkoff + q * 4);
        float4 wv = *(const float4*)(Wr + (size_t)(k0 + wkk) * 4096 + (size_t)wg_ * 1024 + j0 + wq * 4);

        __syncthreads();
#pragma unroll
        for (int q = 0; q < 4; q++) {
            hs[hkoff + q * 4 + 0][hrow] = hv[q].x;
            hs[hkoff + q * 4 + 1][hrow] = hv[q].y;
            hs[hkoff + q * 4 + 2][hrow] = hv[q].z;
            hs[hkoff + q * 4 + 3][hrow] = hv[q].w;
        }
        *(float4*)&ws[wg_][wkk][wq * 4] = wv;
        __syncthreads();

#pragma unroll
        for (int kk = 0; kk < 32; kk++) {
            float4 h4 = *(const float4*)&hs[kk][rq * 4];
            float wi = ws[0][kk][j];
            float wf = ws[1][kk][j];
            float wg2 = ws[2][kk][j];
            float wo = ws[3][kk][j];
            ai[0] += h4.x * wi; ai[1] += h4.y * wi; ai[2] += h4.z * wi; ai[3] += h4.w * wi;
            af[0] += h4.x * wf; af[1] += h4.y * wf; af[2] += h4.z * wf; af[3] += h4.w * wf;
            ag[0] += h4.x * wg2; ag[1] += h4.y * wg2; ag[2] += h4.z * wg2; ag[3] += h4.w * wg2;
            ao[0] += h4.x * wo; ao[1] += h4.y * wo; ao[2] += h4.z * wo; ao[3] += h4.w * wo;
        }
    }

    float* __restrict__ Hnew = g_H + (size_t)(t + 1) * (BSZ * UN);
    const float* __restrict__ zkb = g_ZK + (size_t)t * BSZ * 4096;

#pragma unroll
    for (int i = 0; i < 4; i++) {
        int r = rq * 4 + i;
        size_t zo = (size_t)r * 4096 + j0 + j;
        float zi = ai[i] + zkb[zo];
        float zf = af[i] + zkb[zo + 1024];
        float zg = ag[i] + zkb[zo + 2048];
        float zoo = ao[i] + zkb[zo + 3072];
        size_t ci = (size_t)r * 1024 + j0 + j;
        float c = g_C[ci];
        float si = sigmoidf_(zi);
        float sf = sigmoidf_(zf);
        float so = sigmoidf_(zoo);
        float cn = sf * c + si * tanhf(zg);
        float hn = so * tanhf(cn);
        g_C[ci] = cn;
        Hnew[ci] = hn;
    }
}

extern "C" void kernel_launch(void* const* d_in, const int* in_sizes, int n_in,
                              void* d_out, int out_size)
{
    const float* h0    = (const float*)d_in[0];
    const float* c0    = (const float*)d_in[1];
    const float* X     = (const float*)d_in[2];   // [128, 513, 1024]
    const float* W_emb = (const float*)d_in[3];   // [1024, 1024]
    const float* b_emb = (const float*)d_in[4];
    const float* W_k   = (const float*)d_in[5];   // [1024, 4096]
    const float* W_r   = (const float*)d_in[6];   // [1024, 4096]
    const float* b_r   = (const float*)d_in[7];   // [4096]
    const float* W_out = (const float*)d_in[8];   // [1024, 1024]
    const float* b_out = (const float*)d_in[9];
    (void)in_sizes; (void)n_in; (void)out_size;

    float *pE, *pZK, *pH;
    cudaGetSymbolAddress((void**)&pE, g_E);
    cudaGetSymbolAddress((void**)&pZK, g_ZK);
    cudaGetSymbolAddress((void**)&pH, g_H);

    // 1. state init
    init_state_kernel<<<(BSZ * UN + 255) / 256, 256>>>(h0, c0);

    // 2. E = relu(X @ W_emb + b_emb), all timesteps batched  (M=65536, N=1024)
    {
        dim3 grid(1024 / 128, (TN * BSZ) / 128);
        sgemm_fused<<<grid, 256>>>(X, W_emb, b_emb, pE, 1024, 0);
    }

    // 3. ZK = E @ W_k + b_r, all timesteps batched  (M=65536, N=4096)
    {
        dim3 grid(4096 / 128, (TN * BSZ) / 128);
        sgemm_fused<<<grid, 256>>>(pE, W_k, b_r, pZK, 4096, 1);
    }

    // 4. sequential recurrence (only h @ W_r + pointwise on the critical path)
    for (int t = 0; t < TN; t++) {
        lstm_step_kernel<<<128, 256>>>(W_r, t);
    }

    // 5. OUT = H @ W_out + b_out, all timesteps batched  (M=65536, N=1024)
    {
        dim3 grid(1024 / 128, (TN * BSZ) / 128);
        sgemm_fused<<<grid, 256>>>(pH + (size_t)BSZ * UN, W_out, b_out, (float*)d_out, 1024, 2);
    }
}

// round 4
// speedup vs baseline: 1.7825x; 1.7825x over previous
#include <cuda_runtime.h>
#include <cuda_bf16.h>
#include <mma.h>
#include <cstdint>

using namespace nvcuda;

#define BSZ 128
#define TN  512
#define UN  1024
#define MROWS (TN * BSZ)   // 65536

// ---------------- scratch (static device globals) ----------------
__device__ __nv_bfloat16 g_Xhi[(size_t)MROWS * UN];
__device__ __nv_bfloat16 g_Xlo[(size_t)MROWS * UN];
__device__ __nv_bfloat16 g_Ehi[(size_t)MROWS * UN];
__device__ __nv_bfloat16 g_Elo[(size_t)MROWS * UN];
__device__ float         g_E  [(size_t)MROWS * UN];
__device__ float         g_ZK [(size_t)MROWS * 4 * UN];   // permuted cols p=u*4+g
__device__ float         g_C  [(size_t)BSZ * UN];
__device__ __nv_bfloat16 g_Hhi[(size_t)(TN + 1) * BSZ * UN];
__device__ __nv_bfloat16 g_Hlo[(size_t)(TN + 1) * BSZ * UN];
__device__ __nv_bfloat16 g_Wemb_hi[(size_t)UN * UN];
__device__ __nv_bfloat16 g_Wemb_lo[(size_t)UN * UN];
__device__ __nv_bfloat16 g_Wout_hi[(size_t)UN * UN];
__device__ __nv_bfloat16 g_Wout_lo[(size_t)UN * UN];
__device__ __nv_bfloat16 g_Wk_hi[(size_t)UN * 4 * UN];    // permuted cols
__device__ __nv_bfloat16 g_Wk_lo[(size_t)UN * 4 * UN];
__device__ __nv_bfloat16 g_Wr_hi[(size_t)UN * 4 * UN];    // permuted cols
__device__ __nv_bfloat16 g_Wr_lo[(size_t)UN * 4 * UN];

struct __align__(8) BF4 { __nv_bfloat16 v[4]; };

__device__ __forceinline__ void bsplit(float v, __nv_bfloat16& h, __nv_bfloat16& l) {
    h = __float2bfloat16(v);
    l = __float2bfloat16(v - __bfloat162float(h));
}

// ---------------- prep kernels ----------------
__global__ void split_X(const float* __restrict__ X) {
    size_t i = (size_t)blockIdx.x * 256 + threadIdx.x;   // float4 index
    size_t e = i * 4;
    size_t r = e >> 10;
    int k = (int)(e & 1023);
    int b = (int)(r & 127), t = (int)(r >> 7);
    float4 v = *(const float4*)(X + ((size_t)b * 513 + (size_t)t) * 1024 + k);
    BF4 h, l;
    bsplit(v.x, h.v[0], l.v[0]); bsplit(v.y, h.v[1], l.v[1]);
    bsplit(v.z, h.v[2], l.v[2]); bsplit(v.w, h.v[3], l.v[3]);
    *(BF4*)(g_Xhi + e) = h;
    *(BF4*)(g_Xlo + e) = l;
}

__global__ void split_E(void) {
    size_t i = (size_t)blockIdx.x * 256 + threadIdx.x;
    size_t e = i * 4;
    float4 v = *(const float4*)(g_E + e);
    BF4 h, l;
    bsplit(v.x, h.v[0], l.v[0]); bsplit(v.y, h.v[1], l.v[1]);
    bsplit(v.z, h.v[2], l.v[2]); bsplit(v.w, h.v[3], l.v[3]);
    *(BF4*)(g_Ehi + e) = h;
    *(BF4*)(g_Elo + e) = l;
}

__global__ void split_W(const float* __restrict__ W, __nv_bfloat16* __restrict__ hi,
                        __nv_bfloat16* __restrict__ lo, int N, int perm) {
    size_t i = (size_t)blockIdx.x * 256 + threadIdx.x;
    if (i >= (size_t)1024 * N) return;
    int col = (int)(i % N);
    size_t row = i / N;
    int sc = perm ? ((col & 3) * 1024 + (col >> 2)) : col;
    float v = W[row * N + sc];
    __nv_bfloat16 h, l; bsplit(v, h, l);
    hi[i] = h; lo[i] = l;
}

__global__ void init_state(const float* __restrict__ h0, const float* __restrict__ c0) {
    int i = blockIdx.x * 256 + threadIdx.x;
    if (i < BSZ * UN) {
        g_C[i] = c0[i];
        __nv_bfloat16 h, l; bsplit(h0[i], h, l);
        g_Hhi[i] = h; g_Hlo[i] = l;
    }
}

// ---------------- big bf16-split wmma GEMM ----------------
// D[M,N] = (Ahi+Alo)[M,1024] @ (Bhi+Blo)[1024,N] + bias   (3 bf16 products, fp32 acc)
// mode 0: relu, ldm N         mode 1: ldm N, bias read through unit-major permutation
// mode 2: D=d_out, row r=t*128+b scattered to [b][t][:], ldm TN*1024
__global__ __launch_bounds__(256) void wgemm(
    const __nv_bfloat16* __restrict__ Ahi, const __nv_bfloat16* __restrict__ Alo,
    const __nv_bfloat16* __restrict__ Bhi, const __nv_bfloat16* __restrict__ Blo,
    const float* __restrict__ bias, float* __restrict__ D, int N, int mode)
{
    __shared__ __nv_bfloat16 sAhi[128][40], sAlo[128][40];
    __shared__ __nv_bfloat16 sBhi[32][136], sBlo[32][136];
    __shared__ float sbias[16][128];

    const int tid = threadIdx.x;
    const int n0 = blockIdx.x * 128, m0 = blockIdx.y * 128;
    const int wid = tid >> 5;
    const int wm = wid & 3, wn = wid >> 2;

    for (int i = tid; i < 2048; i += 256) {
        int col = i & 127;
        int p = n0 + col;
        float bv = (mode == 1) ? bias[(p & 3) * 1024 + (p >> 2)] : bias[p];
        sbias[i >> 7][col] = bv;
    }
    __syncthreads();

    wmma::fragment<wmma::accumulator, 16, 16, 16, float> acc[2][4];
#pragma unroll
    for (int i = 0; i < 2; i++)
#pragma unroll
        for (int j = 0; j < 4; j++)
            wmma::load_matrix_sync(acc[i][j], &sbias[0][wn * 64 + j * 16], 128, wmma::mem_row_major);

    const int ar0 = tid >> 2,          as_ = (tid & 3) * 8;
    const int ar1 = (tid + 256) >> 2;
    const int br0 = tid >> 4,          bs_ = (tid & 15) * 8;
    const int br1 = (tid + 256) >> 4;

    for (int k0 = 0; k0 < 1024; k0 += 32) {
        int4 a0h = *(const int4*)(Ahi + (size_t)(m0 + ar0) * 1024 + k0 + as_);
        int4 a1h = *(const int4*)(Ahi + (size_t)(m0 + ar1) * 1024 + k0 + as_);
        int4 a0l = *(const int4*)(Alo + (size_t)(m0 + ar0) * 1024 + k0 + as_);
        int4 a1l = *(const int4*)(Alo + (size_t)(m0 + ar1) * 1024 + k0 + as_);
        int4 b0h = *(const int4*)(Bhi + (size_t)(k0 + br0) * N + n0 + bs_);
        int4 b1h = *(const int4*)(Bhi + (size_t)(k0 + br1) * N + n0 + bs_);
        int4 b0l = *(const int4*)(Blo + (size_t)(k0 + br0) * N + n0 + bs_);
        int4 b1l = *(const int4*)(Blo + (size_t)(k0 + br1) * N + n0 + bs_);
        __syncthreads();
        *(int4*)&sAhi[ar0][as_] = a0h; *(int4*)&sAhi[ar1][as_] = a1h;
        *(int4*)&sAlo[ar0][as_] = a0l; *(int4*)&sAlo[ar1][as_] = a1l;
        *(int4*)&sBhi[br0][bs_] = b0h; *(int4*)&sBhi[br1][bs_] = b1h;
        *(int4*)&sBlo[br0][bs_] = b0l; *(int4*)&sBlo[br1][bs_] = b1l;
        __syncthreads();

#pragma unroll
        for (int kk = 0; kk < 32; kk += 16) {
            wmma::fragment<wmma::matrix_a, 16, 16, 16, __nv_bfloat16, wmma::row_major> ah[2], al[2];
            wmma::fragment<wmma::matrix_b, 16, 16, 16, __nv_bfloat16, wmma::row_major> bh[4], bl[4];
#pragma unroll
            for (int i = 0; i < 2; i++) {
                wmma::load_matrix_sync(ah[i], &sAhi[wm * 32 + i * 16][kk], 40);
                wmma::load_matrix_sync(al[i], &sAlo[wm * 32 + i * 16][kk], 40);
            }
#pragma unroll
            for (int j = 0; j < 4; j++) {
                wmma::load_matrix_sync(bh[j], &sBhi[kk][wn * 64 + j * 16], 136);
                wmma::load_matrix_sync(bl[j], &sBlo[kk][wn * 64 + j * 16], 136);
            }
#pragma unroll
            for (int i = 0; i < 2; i++)
#pragma unroll
                for (int j = 0; j < 4; j++) {
                    wmma::mma_sync(acc[i][j], ah[i], bh[j], acc[i][j]);
                    wmma::mma_sync(acc[i][j], ah[i], bl[j], acc[i][j]);
                    wmma::mma_sync(acc[i][j], al[i], bh[j], acc[i][j]);
                }
        }
    }

#pragma unroll
    for (int i = 0; i < 2; i++)
#pragma unroll
        for (int j = 0; j < 4; j++) {
            if (mode == 0) {
                for (int e = 0; e < acc[i][j].num_elements; e++)
                    acc[i][j].x[e] = fmaxf(acc[i][j].x[e], 0.f);
            }
            int col = n0 + wn * 64 + j * 16;
            if (mode == 2) {
                int t = m0 >> 7;
                int b = wm * 32 + i * 16;
                float* p = D + (size_t)t * 1024 + (size_t)b * ((size_t)TN * 1024) + col;
                wmma::store_matrix_sync(p, acc[i][j], (unsigned)(TN * 1024), wmma::mem_row_major);
            } else {
                int row = m0 + wm * 32 + i * 16;
                wmma::store_matrix_sync(D + (size_t)row * N + col, acc[i][j], N, wmma::mem_row_major);
            }
        }
}

// ---------------- recurrent step: Z = Hsplit @ Wr_split (128 x 4096 x 1024) + gates ----------------
__global__ __launch_bounds__(128) void lstm_step_w(
    const __nv_bfloat16* __restrict__ Whi, const __nv_bfloat16* __restrict__ Wlo, int t)
{
    __shared__ __align__(16) char sm[47104];
    __nv_bfloat16 (*sAhi)[72] = (__nv_bfloat16 (*)[72])(sm);
    __nv_bfloat16 (*sAlo)[72] = (__nv_bfloat16 (*)[72])(sm + 18432);
    __nv_bfloat16 (*sBhi)[40] = (__nv_bfloat16 (*)[40])(sm + 36864);
    __nv_bfloat16 (*sBlo)[40] = (__nv_bfloat16 (*)[40])(sm + 41984);

    const int tid = threadIdx.x, wid = tid >> 5;
    const int n0 = blockIdx.x * 32;
    const __nv_bfloat16* __restrict__ Hhi = g_Hhi + (size_t)t * (BSZ * UN);
    const __nv_bfloat16* __restrict__ Hlo = g_Hlo + (size_t)t * (BSZ * UN);

    wmma::fragment<wmma::accumulator, 16, 16, 16, float> acc[2][2];
#pragma unroll
    for (int i = 0; i < 2; i++)
#pragma unroll
        for (int j = 0; j < 2; j++)
            wmma::fill_fragment(acc[i][j], 0.f);

    const int ar = tid >> 3, as_ = (tid & 7) * 8;
    const int br = tid >> 2, bs_ = (tid & 3) * 8;

    for (int k0 = 0; k0 < 1024; k0 += 64) {
        int4 avh[8], avl[8], bvh[2], bvl[2];
#pragma unroll
        for (int i = 0; i < 8; i++) {
            size_t off = (size_t)(i * 16 + ar) * 1024 + k0 + as_;
            avh[i] = *(const int4*)(Hhi + off);
            avl[i] = *(const int4*)(Hlo + off);
        }
#pragma unroll
        for (int i = 0; i < 2; i++) {
            size_t off = (size_t)(k0 + i * 32 + br) * 4096 + n0 + bs_;
            bvh[i] = *(const int4*)(Whi + off);
            bvl[i] = *(const int4*)(Wlo + off);
        }
        __syncthreads();
#pragma unroll
        for (int i = 0; i < 8; i++) {
            *(int4*)&sAhi[i * 16 + ar][as_] = avh[i];
            *(int4*)&sAlo[i * 16 + ar][as_] = avl[i];
        }
#pragma unroll
        for (int i = 0; i < 2; i++) {
            *(int4*)&sBhi[i * 32 + br][bs_] = bvh[i];
            *(int4*)&sBlo[i * 32 + br][bs_] = bvl[i];
        }
        __syncthreads();

#pragma unroll
        for (int kk = 0; kk < 64; kk += 16) {
            wmma::fragment<wmma::matrix_a, 16, 16, 16, __nv_bfloat16, wmma::row_major> ah[2], al[2];
            wmma::fragment<wmma::matrix_b, 16, 16, 16, __nv_bfloat16, wmma::row_major> bh[2], bl[2];
#pragma unroll
            for (int i = 0; i < 2; i++) {
                wmma::load_matrix_sync(ah[i], &sAhi[wid * 32 + i * 16][kk], 72);
                wmma::load_matrix_sync(al[i], &sAlo[wid * 32 + i * 16][kk], 72);
            }
#pragma unroll
            for (int j = 0; j < 2; j++) {
                wmma::load_matrix_sync(bh[j], &sBhi[kk][j * 16], 40);
                wmma::load_matrix_sync(bl[j], &sBlo[kk][j * 16], 40);
            }
#pragma unroll
            for (int i = 0; i < 2; i++)
#pragma unroll
                for (int j = 0; j < 2; j++) {
                    wmma::mma_sync(acc[i][j], ah[i], bh[j], acc[i][j]);
                    wmma::mma_sync(acc[i][j], ah[i], bl[j], acc[i][j]);
                    wmma::mma_sync(acc[i][j], al[i], bh[j], acc[i][j]);
                }
        }
        __syncthreads();
    }

    float (*z)[36] = (float (*)[36])sm;
#pragma unroll
    for (int i = 0; i < 2; i++)
#pragma unroll
        for (int j = 0; j < 2; j++)
            wmma::store_matrix_sync(&z[wid * 32 + i * 16][j * 16], acc[i][j], 36, wmma::mem_row_major);
    __syncthreads();

    const int m = tid;
    const float* __restrict__ zk = g_ZK + ((size_t)t * BSZ + m) * 4096 + n0;
    float* __restrict__ cp = g_C + (size_t)m * UN + blockIdx.x * 8;
    size_t hoff = (size_t)(t + 1) * (BSZ * UN) + (size_t)m * UN + blockIdx.x * 8;

    float cv[8];
    *(float4*)(cv)     = *(const float4*)(cp);
    *(float4*)(cv + 4) = *(const float4*)(cp + 4);

    BF4 hh[2], hl[2];
#pragma unroll
    for (int u = 0; u < 8; u++) {
        float4 zk4 = *(const float4*)(zk + u * 4);
        float zi = z[m][u * 4 + 0] + zk4.x;
        float zf = z[m][u * 4 + 1] + zk4.y;
        float zg = z[m][u * 4 + 2] + zk4.z;
        float zo = z[m][u * 4 + 3] + zk4.w;
        float si = 1.f / (1.f + __expf(-zi));
        float sf = 1.f / (1.f + __expf(-zf));
        float so = 1.f / (1.f + __expf(-zo));
        float cn = sf * cv[u] + si * tanhf(zg);
        float hn = so * tanhf(cn);
        cv[u] = cn;
        bsplit(hn, hh[u >> 2].v[u & 3], hl[u >> 2].v[u & 3]);
    }
    *(float4*)(cp)     = *(const float4*)(cv);
    *(float4*)(cp + 4) = *(const float4*)(cv + 4);
    *(BF4*)(g_Hhi + hoff)     = hh[0];
    *(BF4*)(g_Hhi + hoff + 4) = hh[1];
    *(BF4*)(g_Hlo + hoff)     = hl[0];
    *(BF4*)(g_Hlo + hoff + 4) = hl[1];
}

// ---------------- host ----------------
extern "C" void kernel_launch(void* const* d_in, const int* in_sizes, int n_in,
                              void* d_out, int out_size)
{
    const float* h0    = (const float*)d_in[0];
    const float* c0    = (const float*)d_in[1];
    const float* X     = (const float*)d_in[2];
    const float* W_emb = (const float*)d_in[3];
    const float* b_emb = (const float*)d_in[4];
    const float* W_k   = (const float*)d_in[5];
    const float* W_r   = (const float*)d_in[6];
    const float* b_r   = (const float*)d_in[7];
    const float* W_out = (const float*)d_in[8];
    const float* b_out = (const float*)d_in[9];
    (void)in_sizes; (void)n_in; (void)out_size;

    __nv_bfloat16 *pXhi, *pXlo, *pEhi, *pElo, *pHhi, *pHlo;
    __nv_bfloat16 *pWembh, *pWembl, *pWouth, *pWoutl, *pWkh, *pWkl, *pWrh, *pWrl;
    float *pE, *pZK;
    cudaGetSymbolAddress((void**)&pXhi, g_Xhi);
    cudaGetSymbolAddress((void**)&pXlo, g_Xlo);
    cudaGetSymbolAddress((void**)&pEhi, g_Ehi);
    cudaGetSymbolAddress((void**)&pElo, g_Elo);
    cudaGetSymbolAddress((void**)&pHhi, g_Hhi);
    cudaGetSymbolAddress((void**)&pHlo, g_Hlo);
    cudaGetSymbolAddress((void**)&pWembh, g_Wemb_hi);
    cudaGetSymbolAddress((void**)&pWembl, g_Wemb_lo);
    cudaGetSymbolAddress((void**)&pWouth, g_Wout_hi);
    cudaGetSymbolAddress((void**)&pWoutl, g_Wout_lo);
    cudaGetSymbolAddress((void**)&pWkh, g_Wk_hi);
    cudaGetSymbolAddress((void**)&pWkl, g_Wk_lo);
    cudaGetSymbolAddress((void**)&pWrh, g_Wr_hi);
    cudaGetSymbolAddress((void**)&pWrl, g_Wr_lo);
    cudaGetSymbolAddress((void**)&pE, g_E);
    cudaGetSymbolAddress((void**)&pZK, g_ZK);

    split_X<<<(int)((size_t)MROWS * UN / 4 / 256), 256>>>(X);
    split_W<<<(1024 * 1024 + 255) / 256, 256>>>(W_emb, pWembh, pWembl, 1024, 0);
    split_W<<<(1024 * 1024 + 255) / 256, 256>>>(W_out, pWouth, pWoutl, 1024, 0);
    split_W<<<(1024 * 4096 + 255) / 256, 256>>>(W_k, pWkh, pWkl, 4096, 1);
    split_W<<<(1024 * 4096 + 255) / 256, 256>>>(W_r, pWrh, pWrl, 4096, 1);
    init_state<<<(BSZ * UN + 255) / 256, 256>>>(h0, c0);

    {   // E = relu(X @ W_emb + b_emb)
        dim3 grid(1024 / 128, MROWS / 128);
        wgemm<<<grid, 256>>>(pXhi, pXlo, pWembh, pWembl, b_emb, pE, 1024, 0);
    }
    split_E<<<(int)((size_t)MROWS * UN / 4 / 256), 256>>>();

    {   // ZK = E @ W_k + b_r (unit-major permuted columns)
        dim3 grid(4096 / 128, MROWS / 128);
        wgemm<<<grid, 256>>>(pEhi, pElo, pWkh, pWkl, b_r, pZK, 4096, 1);
    }

    for (int t = 0; t < TN; t++)
        lstm_step_w<<<128, 128>>>(pWrh, pWrl, t);

    {   // OUT = H @ W_out + b_out, scattered to [b][t][:]
        dim3 grid(1024 / 128, MROWS / 128);
        wgemm<<<grid, 256>>>(pHhi + (size_t)BSZ * UN, pHlo + (size_t)BSZ * UN,
                             pWouth, pWoutl, b_out, (float*)d_out, 1024, 2);
    }
}